// round 4
// baseline (speedup 1.0000x reference)
#include <cuda_runtime.h>
#include <cstdint>
#include <math.h>

// Problem constants
#define Bb   256
#define Tt   1024
#define Ii   8
#define Hh   164
#define JH   82          // hidden slice per CTA (M-split across 2-CTA cluster)
#define KPP  84          // padded k-pairs (82 real + 2 zero)
#define QK   21          // k-pairs per quarter
#define RKQ  8           // k-pairs in registers
#define SKQ  (QK - RKQ)  // 13 k-pairs in smem
#define CT   656         // compute threads: 4 quarters x 164 row-pairs
#define NTH  672         // 21 warps
#define NCTA 128         // 64 clusters x 2

// shared memory layout (bytes)
#define OFF_WSM   0
#define SZ_WSM    (SKQ * CT * 16)           // 136448: Wsm[kks][tid] = (wA,wB) ulonglong2
#define OFF_HQ    (OFF_WSM + SZ_WSM)
#define SZ_HQ     (2 * KPP * 32)            // 5376: h double-buffered, 32B/k-pair
#define OFF_GB    (OFF_HQ + SZ_HQ)
#define SZ_GB     (8 * 164 * 16)            // 20992: gate partials float4[(q*2+ab)][g]
#define OFF_PW    (OFF_GB + SZ_GB)
#define SZ_PW     (2 * 2 * 12 * 16)         // 768: pred warp partials [par][side][w][r]
#define OFF_XQ    (OFF_PW + SZ_PW)
#define SZ_XQ     (2 * Ii * 16)             // 256: x double-buffered [par][i][r]
#define OFF_W0    (OFF_XQ + SZ_XQ)
#define SZ_W0     (5 * JH * 4)              // 1640: wih0[gate][jj] + wout[jj]
#define OFF_WIHS  ((OFF_W0 + SZ_W0 + 15) & ~15)
#define SZ_WIHS   (14 * 164 * 4)            // 9184: wih[(ab*7+i-1)][g]
#define OFF_MBAR  ((OFF_WIHS + SZ_WIHS + 7) & ~7)
#define SMEM_TOTAL (OFF_MBAR + 16)          // ~174.7 KB

typedef unsigned long long ull;

__device__ __forceinline__ float sigmoidf_(float v) {
    return 1.0f / (1.0f + expf(-v));
}
__device__ __forceinline__ ull pack2_(float a, float b) {
    ull r; asm("mov.b64 %0, {%1, %2};" : "=l"(r) : "f"(a), "f"(b)); return r;
}
__device__ __forceinline__ void unpack2_(ull v, float& a, float& b) {
    asm("mov.b64 {%0, %1}, %2;" : "=f"(a), "=f"(b) : "l"(v));
}
__device__ __forceinline__ void fma2_(ull& acc, ull a, ull b) {
    asm("fma.rn.f32x2 %0, %1, %2, %0;" : "+l"(acc) : "l"(a), "l"(b));
}
__device__ __forceinline__ void st_remote_f32(uint32_t local_addr, uint32_t peer, float v) {
    uint32_t ra;
    asm("mapa.shared::cluster.u32 %0, %1, %2;" : "=r"(ra) : "r"(local_addr), "r"(peer));
    asm volatile("st.shared::cluster.f32 [%0], %1;" :: "r"(ra), "f"(v) : "memory");
}
__device__ __forceinline__ void mbar_arrive_peer(uint32_t local_mbar, uint32_t peer) {
    asm volatile(
        "{\n\t.reg .b32 ra;\n\t"
        "mapa.shared::cluster.u32 ra, %0, %1;\n\t"
        "mbarrier.arrive.release.cluster.shared::cluster.b64 _, [ra];\n\t}"
        :: "r"(local_mbar), "r"(peer) : "memory");
}
__device__ __forceinline__ void mbar_wait(uint32_t mbar, uint32_t parity) {
    uint32_t done;
    asm volatile(
        "{\n\t.reg .pred p;\n\t"
        "mbarrier.try_wait.parity.acquire.cluster.shared::cta.b64 p, [%1], %2;\n\t"
        "selp.b32 %0, 1, 0, p;\n\t}"
        : "=r"(done) : "r"(mbar), "r"(parity) : "memory");
    while (!done) {
        asm volatile(
            "{\n\t.reg .pred p;\n\t"
            "mbarrier.try_wait.parity.acquire.cluster.shared::cta.b64 p, [%1], %2, 0x989680;\n\t"
            "selp.b32 %0, 1, 0, p;\n\t}"
            : "=r"(done) : "r"(mbar), "r"(parity) : "memory");
    }
}

extern "C" __global__ void __launch_bounds__(NTH, 1) __cluster_dims__(2, 1, 1)
lstm_anom_kernel(const float* __restrict__ x,
                 const float* __restrict__ Wih,
                 const float* __restrict__ Whh,
                 const float* __restrict__ bih,
                 const float* __restrict__ bhh,
                 const float* __restrict__ Wout,
                 const float* __restrict__ bout,
                 float* __restrict__ out)
{
    extern __shared__ char smem[];
    ulonglong2* Wsm2 = (ulonglong2*)(smem + OFF_WSM);
    float4* gb4  = (float4*)(smem + OFF_GB);
    const float* gbf = (const float*)(smem + OFF_GB);
    float*  pwf  = (float*)(smem + OFF_PW);
    float*  xqf  = (float*)(smem + OFF_XQ);
    float*  w0f  = (float*)(smem + OFF_W0);      // [gate*82+jj], wout at [4*82+jj]
    float*  wihs = (float*)(smem + OFF_WIHS);    // [(ab*7 + i-1)*164 + g]

    const int tid       = threadIdx.x;
    const uint32_t rank = (uint32_t)(blockIdx.x & 1);
    const uint32_t peer = rank ^ 1u;
    const int cluster   = blockIdx.x >> 1;
    const int row0      = cluster * 4;

    const uint32_t smem_b = (uint32_t)__cvta_generic_to_shared(smem);
    const uint32_t mbar_b = smem_b + OFF_MBAR;

    // ---------- one-time init ----------
    const int q  = tid / 164;            // k-quarter (4 == spare threads)
    const int g  = tid - q * 164;        // gate-row-pair id
    ull wregA[RKQ], wregB[RKQ];
    float biasA = 0.f, biasB = 0.f;
    if (tid < CT) {
        int gt  = g / JH;
        int jj0 = g - gt * JH;
        int RA  = gt * Hh + (int)rank * JH + jj0;        // i or f gate row
        int RB  = (gt + 2) * Hh + (int)rank * JH + jj0;  // g or o gate row
        const ull* wrA = (const ull*)(Whh + (size_t)RA * Hh);
        const ull* wrB = (const ull*)(Whh + (size_t)RB * Hh);
#pragma unroll
        for (int kk = 0; kk < QK; kk++) {
            int kp = q * QK + kk;
            ull vA = (kp < 82) ? wrA[kp] : 0ull;
            ull vB = (kp < 82) ? wrB[kp] : 0ull;
            if (kk < RKQ) { wregA[kk] = vA; wregB[kk] = vB; }
            else          Wsm2[(kk - RKQ) * CT + tid] = make_ulonglong2(vA, vB);
        }
        if (q == 0) {
#pragma unroll
            for (int i = 1; i < Ii; i++) {
                wihs[(0 * 7 + i - 1) * 164 + g] = Wih[RA * Ii + i];
                wihs[(1 * 7 + i - 1) * 164 + g] = Wih[RB * Ii + i];
            }
            biasA = bih[RA] + bhh[RA];
            biasB = bih[RB] + bhh[RB];
        }
    }
    if (tid < JH) {
        int base = (int)rank * JH + tid;
#pragma unroll
        for (int gate = 0; gate < 4; gate++)
            w0f[gate * JH + tid] = Wih[(gate * Hh + base) * Ii];
        w0f[4 * JH + tid] = Wout[base];
    }
    const int jj = tid >> 2, rr = tid & 3;     // activation role (tid < 328)
    float c_r = 0.f;
    const float bout_r = bout[0];

    for (int idx = tid; idx < (SZ_HQ / 4); idx += NTH)
        ((float*)(smem + OFF_HQ))[idx] = 0.f;
    for (int idx = tid; idx < (SZ_PW / 4); idx += NTH) pwf[idx] = 0.f;
    if (tid < 32) {
        int i = tid >> 2, r = tid & 3;
        xqf[(0 * Ii + i) * 4 + r] = x[((size_t)((row0 + r) * Tt)) * Ii + i];
    }
    if (tid == 0) {
        asm volatile("mbarrier.init.shared.b64 [%0], 1;" :: "r"(mbar_b) : "memory");
        asm volatile("mbarrier.init.shared.b64 [%0], 1;" :: "r"(mbar_b + 8) : "memory");
    }
    __syncthreads();
    asm volatile("barrier.cluster.arrive.aligned;" ::: "memory");
    asm volatile("barrier.cluster.wait.aligned;" ::: "memory");

    const int wid = tid >> 5, lane = tid & 31;

    for (int t = 0; t < Tt; ++t) {
        const int cur = t & 1;
        const int nxt = cur ^ 1;

        if (t) mbar_wait(mbar_b + (uint32_t)(((t - 1) & 1) * 8), (uint32_t)(((t - 1) >> 1) & 1));

        if (tid < CT) {
            // ---- GEMV over own k-quarter ----
            ull accA[4], accB[4];
            if (q == 0) {
                float a0 = biasA, a1 = biasA, a2 = biasA, a3 = biasA;
                float b0 = biasB, b1 = biasB, b2 = biasB, b3 = biasB;
                const float4* xv4 = (const float4*)(smem + OFF_XQ + cur * 128);
#pragma unroll
                for (int i = 1; i < Ii; i++) {
                    float4 xv = xv4[i];
                    float wA = wihs[(0 * 7 + i - 1) * 164 + g];
                    float wB = wihs[(1 * 7 + i - 1) * 164 + g];
                    a0 += wA * xv.x; a1 += wA * xv.y; a2 += wA * xv.z; a3 += wA * xv.w;
                    b0 += wB * xv.x; b1 += wB * xv.y; b2 += wB * xv.z; b3 += wB * xv.w;
                }
                accA[0] = pack2_(a0, 0.f); accA[1] = pack2_(a1, 0.f);
                accA[2] = pack2_(a2, 0.f); accA[3] = pack2_(a3, 0.f);
                accB[0] = pack2_(b0, 0.f); accB[1] = pack2_(b1, 0.f);
                accB[2] = pack2_(b2, 0.f); accB[3] = pack2_(b3, 0.f);
            } else {
#pragma unroll
                for (int s = 0; s < 4; s++) { accA[s] = 0ull; accB[s] = 0ull; }
            }
            const ulonglong2* hp =
                (const ulonglong2*)(smem + OFF_HQ + cur * (KPP * 32)) + q * (QK * 2);
#pragma unroll
            for (int kk = 0; kk < RKQ; kk++) {
                ulonglong2 h01 = hp[2 * kk];
                ulonglong2 h23 = hp[2 * kk + 1];
                fma2_(accA[0], wregA[kk], h01.x); fma2_(accB[0], wregB[kk], h01.x);
                fma2_(accA[1], wregA[kk], h01.y); fma2_(accB[1], wregB[kk], h01.y);
                fma2_(accA[2], wregA[kk], h23.x); fma2_(accB[2], wregB[kk], h23.x);
                fma2_(accA[3], wregA[kk], h23.y); fma2_(accB[3], wregB[kk], h23.y);
            }
#pragma unroll
            for (int kk = RKQ; kk < QK; kk++) {
                ulonglong2 w2 = Wsm2[(kk - RKQ) * CT + tid];
                ulonglong2 h01 = hp[2 * kk];
                ulonglong2 h23 = hp[2 * kk + 1];
                fma2_(accA[0], w2.x, h01.x); fma2_(accB[0], w2.y, h01.x);
                fma2_(accA[1], w2.x, h01.y); fma2_(accB[1], w2.y, h01.y);
                fma2_(accA[2], w2.x, h23.x); fma2_(accB[2], w2.y, h23.x);
                fma2_(accA[3], w2.x, h23.y); fma2_(accB[3], w2.y, h23.y);
            }
            float lo, hi;
            float4 vA, vB;
            unpack2_(accA[0], lo, hi); vA.x = lo + hi;
            unpack2_(accA[1], lo, hi); vA.y = lo + hi;
            unpack2_(accA[2], lo, hi); vA.z = lo + hi;
            unpack2_(accA[3], lo, hi); vA.w = lo + hi;
            unpack2_(accB[0], lo, hi); vB.x = lo + hi;
            unpack2_(accB[1], lo, hi); vB.y = lo + hi;
            unpack2_(accB[2], lo, hi); vB.z = lo + hi;
            unpack2_(accB[3], lo, hi); vB.w = lo + hi;
            gb4[(q * 2 + 0) * 164 + g] = vA;
            gb4[(q * 2 + 1) * 164 + g] = vB;
        } else {
            // ---- spare threads: pred finalize, anomaly fix, x prefetch ----
            int sp = tid - CT;
            if (sp < 4) {
                int r = sp, row = row0 + r;
                int prev = cur ^ 1;
                if (t > 0) {
                    float pred = bout_r;
#pragma unroll
                    for (int w = 0; w < 11; w++) {
                        pred += pwf[((prev * 2 + 0) * 12 + w) * 4 + r];
                        pred += pwf[((prev * 2 + 1) * 12 + w) * 4 + r];
                    }
                    float x0raw = xqf[(cur * Ii + 0) * 4 + r];
                    float flag = 0.f, x0 = x0raw;
                    if (fabsf(pred - x0raw) > 0.1f) { x0 = pred; flag = 1.f; }
                    xqf[(cur * Ii + 0) * 4 + r] = x0;
                    if (rank == 0) {
                        out[(size_t)row * Tt + (t - 1)] = pred;
                        out[(size_t)Bb * Tt + (size_t)row * Tt + t] = flag;
                    }
#pragma unroll
                    for (int w = 0; w < 11; w++) {
                        pwf[((prev * 2 + 0) * 12 + w) * 4 + r] = 0.f;
                        pwf[((prev * 2 + 1) * 12 + w) * 4 + r] = 0.f;
                    }
                } else {
                    if (rank == 0)
                        out[(size_t)Bb * Tt + (size_t)row * Tt + 0] = 0.f;
                }
            } else if (sp >= 8 && (t + 1 < Tt)) {
                int i = sp - 8;                       // 8 threads, i = 0..7
#pragma unroll
                for (int r = 0; r < 4; r++)
                    xqf[(nxt * Ii + i) * 4 + r] =
                        x[((size_t)((row0 + r) * Tt + t + 1)) * Ii + i];
            }
        }
        __syncthreads();   // gate partials + fixed x0 published

        // ---- activation, state update, h exchange, pred partials ----
        if (tid < 328) {
            float x0 = xqf[(cur * Ii + 0) * 4 + rr];
            float gi = gbf[((0 * 2 + 0) * 164 + jj) * 4 + rr]
                     + gbf[((1 * 2 + 0) * 164 + jj) * 4 + rr]
                     + gbf[((2 * 2 + 0) * 164 + jj) * 4 + rr]
                     + gbf[((3 * 2 + 0) * 164 + jj) * 4 + rr] + w0f[0 * JH + jj] * x0;
            float gF = gbf[((0 * 2 + 0) * 164 + jj + 82) * 4 + rr]
                     + gbf[((1 * 2 + 0) * 164 + jj + 82) * 4 + rr]
                     + gbf[((2 * 2 + 0) * 164 + jj + 82) * 4 + rr]
                     + gbf[((3 * 2 + 0) * 164 + jj + 82) * 4 + rr] + w0f[1 * JH + jj] * x0;
            float gg = gbf[((0 * 2 + 1) * 164 + jj) * 4 + rr]
                     + gbf[((1 * 2 + 1) * 164 + jj) * 4 + rr]
                     + gbf[((2 * 2 + 1) * 164 + jj) * 4 + rr]
                     + gbf[((3 * 2 + 1) * 164 + jj) * 4 + rr] + w0f[2 * JH + jj] * x0;
            float go = gbf[((0 * 2 + 1) * 164 + jj + 82) * 4 + rr]
                     + gbf[((1 * 2 + 1) * 164 + jj + 82) * 4 + rr]
                     + gbf[((2 * 2 + 1) * 164 + jj + 82) * 4 + rr]
                     + gbf[((3 * 2 + 1) * 164 + jj + 82) * 4 + rr] + w0f[3 * JH + jj] * x0;
            float iv = sigmoidf_(gi);
            float fv = sigmoidf_(gF);
            float gv = tanhf(gg);
            float ov = sigmoidf_(go);
            c_r = fv * c_r + iv * gv;
            float hn = ov * tanhf(c_r);

            int kg = (int)rank * JH + jj;
            uint32_t hoff = (uint32_t)(OFF_HQ + nxt * (KPP * 32)
                                       + (kg >> 1) * 32 + rr * 8 + (kg & 1) * 4);
            *(float*)(smem + hoff) = hn;
            st_remote_f32(smem_b + hoff, peer, hn);

            float p = hn * w0f[4 * JH + jj];
            if (wid < 10) {
                p += __shfl_xor_sync(0xffffffffu, p, 16);
                p += __shfl_xor_sync(0xffffffffu, p, 8);
                p += __shfl_xor_sync(0xffffffffu, p, 4);
            } else {
                p += __shfl_xor_sync(0xffu, p, 4);
            }
            if (lane < 4) {
                uint32_t po0 = (uint32_t)(OFF_PW + (((cur * 2 + 0) * 12 + wid) * 4 + lane) * 4);
                uint32_t po1 = (uint32_t)(OFF_PW + (((cur * 2 + 1) * 12 + wid) * 4 + lane) * 4);
                *(float*)(smem + po0) = p;
                st_remote_f32(smem_b + po1, peer, p);
            }
        }
        __syncthreads();

        if (tid == 0) mbar_arrive_peer(mbar_b + (uint32_t)(cur * 8), peer);
    }

    // ---- tail: final prediction at column Tt-1 ----
    mbar_wait(mbar_b + (uint32_t)(((Tt - 1) & 1) * 8), (uint32_t)(((Tt - 1) >> 1) & 1));
    if (rank == 0 && tid < 4) {
        int par = (Tt - 1) & 1;
        float pred = bout_r;
#pragma unroll
        for (int w = 0; w < 11; w++) {
            pred += pwf[((par * 2 + 0) * 12 + w) * 4 + tid];
            pred += pwf[((par * 2 + 1) * 12 + w) * 4 + tid];
        }
        out[(size_t)(row0 + tid) * Tt + (Tt - 1)] = pred;
    }
}

extern "C" void kernel_launch(void* const* d_in, const int* in_sizes, int n_in,
                              void* d_out, int out_size) {
    (void)in_sizes; (void)n_in; (void)out_size;
    cudaFuncSetAttribute(lstm_anom_kernel,
                         cudaFuncAttributeMaxDynamicSharedMemorySize, SMEM_TOTAL);
    lstm_anom_kernel<<<NCTA, NTH, SMEM_TOTAL>>>(
        (const float*)d_in[0],   // x
        (const float*)d_in[1],   // W_ih
        (const float*)d_in[2],   // W_hh
        (const float*)d_in[3],   // b_ih
        (const float*)d_in[4],   // b_hh
        (const float*)d_in[5],   // W_out
        (const float*)d_in[6],   // b_out
        (float*)d_out);
}